// round 16
// baseline (speedup 1.0000x reference)
#include <cuda_runtime.h>
#include <cuda_fp16.h>
#include <stdint.h>

#define SEQ    512
#define HID    768
#define HEADS  12
#define DH     64
#define LAYERS 12
#define BATCH  32
#define ROWS   (BATCH * SEQ)   /* 16384 */
#define LN_EPS 1e-12f

#define KT   32                 /* fp16 k per stage            */
#define RSE  40                 /* smem row stride, elements   */
#define RSB  80                 /* smem row stride, bytes      */
#define BUFB (128 * RSB)        /* one operand buffer: 10240 B */
#define STAGEB (2 * BUFB)       /* A, B: 20480 B               */
#define NSTAGE 4
#define OFF_A 0
#define OFF_B BUFB
#define SMEM_DYN (NSTAGE * STAGEB)   /* 81920 B (>= 128*136*2 fp16 stage) */

#define NGRP 8                  /* batch groups (parallel graph branches) */
#define GBATCH (BATCH / NGRP)   /* 4 batches per group */

/* ------------------------- device scratch (static) ------------------------ */
__device__ __half g_hA[(size_t)ROWS * HID];
__device__ __half g_Xt[(size_t)ROWS * HID];   /* [B*HEADS*DH][SEQ] */
__device__ __half g_W[(size_t)(LAYERS + 1) * HID * HID];
__device__ __half g_Mt[(size_t)LAYERS * HEADS * SEQ * SEQ];

/* ---------------- streams/events (created at static init) ----------------- */
struct GraphForkRes {
    cudaStream_t s[NGRP];
    cudaStream_t p[2];
    cudaEvent_t  fork;
    cudaEvent_t  w0;      /* layer-0 W converted      */
    cudaEvent_t  pro0;    /* all W converted          */
    cudaEvent_t  pro1;    /* Mt transposed            */
    cudaEvent_t  emb;     /* embeddings done          */
    cudaEvent_t  join[NGRP];
    GraphForkRes() {
        for (int i = 0; i < NGRP; i++)
            cudaStreamCreateWithFlags(&s[i], cudaStreamNonBlocking);
        for (int i = 0; i < 2; i++)
            cudaStreamCreateWithFlags(&p[i], cudaStreamNonBlocking);
        cudaEventCreateWithFlags(&fork, cudaEventDisableTiming);
        cudaEventCreateWithFlags(&w0, cudaEventDisableTiming);
        cudaEventCreateWithFlags(&pro0, cudaEventDisableTiming);
        cudaEventCreateWithFlags(&pro1, cudaEventDisableTiming);
        cudaEventCreateWithFlags(&emb, cudaEventDisableTiming);
        for (int i = 0; i < NGRP; i++)
            cudaEventCreateWithFlags(&join[i], cudaEventDisableTiming);
    }
};
static GraphForkRes g_fork;

/* ------------------------------ PTX helpers ------------------------------ */
__device__ __forceinline__ uint32_t smem_u32(const void* p) {
    uint32_t a;
    asm("{ .reg .u64 t; cvta.to.shared.u64 t, %1; cvt.u32.u64 %0, t; }"
        : "=r"(a) : "l"(p));
    return a;
}
__device__ __forceinline__ void cpa16(uint32_t dst, const void* src) {
    asm volatile("cp.async.cg.shared.global [%0], [%1], 16;"
                 :: "r"(dst), "l"(src) : "memory");
}
__device__ __forceinline__ void cp_commit() {
    asm volatile("cp.async.commit_group;" ::: "memory");
}
__device__ __forceinline__ void cp_wait1() {
    asm volatile("cp.async.wait_group 1;" ::: "memory");
}
__device__ __forceinline__ void cp_wait0() {
    asm volatile("cp.async.wait_group 0;" ::: "memory");
}
__device__ __forceinline__ void ldm_x4(uint32_t* r, uint32_t addr) {
    asm volatile("ldmatrix.sync.aligned.m8n8.x4.shared.b16 {%0,%1,%2,%3}, [%4];"
                 : "=r"(r[0]), "=r"(r[1]), "=r"(r[2]), "=r"(r[3]) : "r"(addr));
}
__device__ __forceinline__ void mma16816(float* c, const uint32_t* a, const uint32_t* b) {
    asm volatile(
        "mma.sync.aligned.m16n8k16.row.col.f32.f16.f16.f32 "
        "{%0,%1,%2,%3},{%4,%5,%6,%7},{%8,%9},{%0,%1,%2,%3};"
        : "+f"(c[0]), "+f"(c[1]), "+f"(c[2]), "+f"(c[3])
        : "r"(a[0]), "r"(a[1]), "r"(a[2]), "r"(a[3]), "r"(b[0]), "r"(b[1]));
}

/* ------------------------------ stage loaders ----------------------------- */
__device__ __forceinline__ void stage_load_dense(
    uint32_t sm, const __half* A, const __half* W, int m0, int n0, int k0)
{
    int tid = threadIdx.x;
#pragma unroll
    for (int i = 0; i < 4; i++) {
        const int buf = i >> 1;
        int rem = tid + (i & 1) * 256;
        int row = rem >> 2;
        int c   = rem & 3;
        const __half* src = buf
            ? W + (size_t)(n0 + row) * HID + k0 + c * 8
            : A + (size_t)(m0 + row) * HID + k0 + c * 8;
        cpa16(sm + buf * BUFB + row * RSB + c * 16, src);
    }
}
__device__ __forceinline__ void stage_load_mix(
    uint32_t sm, const __half* M, const __half* X,
    int t0, int h, int b0, int s0)
{
    int tid = threadIdx.x;
#pragma unroll
    for (int i = 0; i < 4; i++) {
        const int buf = i >> 1;
        int rem = tid + (i & 1) * 256;
        int row = rem >> 2;
        int c   = rem & 3;
        const __half* src;
        if (buf == 0) {
            src = M + (size_t)(t0 + row) * SEQ + s0 + c * 8;
        } else {
            int bb = row >> 6, d = row & 63;
            size_t R = ((size_t)(b0 + bb) * HEADS + h) * DH + d;
            src = X + R * SEQ + s0 + c * 8;
        }
        cpa16(sm + buf * BUFB + row * RSB + c * 16, src);
    }
}

/* ------------------------------- MMA core -------------------------------- */
/* 8 warps, each 32m x 64n; acc[16][4]. */
__device__ __forceinline__ void load_frags(
    uint32_t sbase, int ks, int wm, int wn, int lane,
    uint32_t* af, uint32_t* bf)
{
    const int ar = lane & 15;
    const int ac = (lane >> 4) * 8;
    const int br = ((lane >> 4) << 3) + (lane & 7);
    const int bc = ((lane >> 3) & 1) * 8;
#pragma unroll
    for (int mi = 0; mi < 2; mi++) {
        uint32_t off = ((wm * 32 + mi * 16 + ar) * RSE + ks * 16 + ac) * 2;
        ldm_x4(af + 4 * mi, sbase + OFF_A + off);
    }
#pragma unroll
    for (int nh = 0; nh < 2; nh++)
#pragma unroll
        for (int g = 0; g < 2; g++) {
            uint32_t off = ((wn * 64 + nh * 32 + g * 16 + br) * RSE + ks * 16 + bc) * 2;
            ldm_x4(bf + nh * 8 + 4 * g, sbase + OFF_B + off);
        }
}
__device__ __forceinline__ void mma_frags(
    float (*acc)[4], const uint32_t* af, const uint32_t* bf)
{
#pragma unroll
    for (int nh = 0; nh < 2; nh++)
#pragma unroll
        for (int mi = 0; mi < 2; mi++)
#pragma unroll
            for (int nj = 0; nj < 4; nj++)
                mma16816(acc[mi * 8 + nh * 4 + nj], af + 4 * mi, bf + nh * 8 + 2 * nj);
}

/* --------------------------- dense tensor GEMM ---------------------------- */
template <bool FINAL>
__global__ void __launch_bounds__(256, 2) gemm_dense_kernel(
    const __half* __restrict__ A, const __half* __restrict__ W,
    const float* __restrict__ bias,
    __half* __restrict__ Oh, float* __restrict__ Of, int m_base)
{
    extern __shared__ __align__(16) char smem[];
    uint32_t sb = smem_u32(smem);
    int tid = threadIdx.x, lane = tid & 31, wid = tid >> 5;
    int wm = wid & 3, wn = wid >> 2;
    int n0 = blockIdx.x * 128, m0 = m_base + blockIdx.y * 128;

    float acc[16][4];
#pragma unroll
    for (int i = 0; i < 16; i++)
#pragma unroll
        for (int j = 0; j < 4; j++) acc[i][j] = 0.f;

    const int NK = HID / KT;   /* 24 */
    stage_load_dense(sb,          A, W, m0, n0, 0);  cp_commit();
    stage_load_dense(sb + STAGEB, A, W, m0, n0, KT); cp_commit();

    for (int i = 0; i < NK; i++) {
        if (i + 1 < NK) cp_wait1(); else cp_wait0();
        if ((i & 1) == 0) __syncthreads();
        uint32_t sbase = sb + (i & 3) * STAGEB;
        uint32_t af[8], bf[16];
        load_frags(sbase, 0, wm, wn, lane, af, bf);
        if (i + 2 < NK) {
            stage_load_dense(sb + ((i + 2) & 3) * STAGEB, A, W, m0, n0, (i + 2) * KT);
            cp_commit();
        }
        mma_frags(acc, af, bf);
        load_frags(sbase, 1, wm, wn, lane, af, bf);
        mma_frags(acc, af, bf);
    }

    if (FINAL) {
        const int r0 = wm * 32 + (lane >> 2);
        const int c0 = wn * 64 + (lane & 3) * 2;
#pragma unroll
        for (int mi = 0; mi < 2; mi++)
#pragma unroll
            for (int njj = 0; njj < 8; njj++) {
                int m = m0 + r0 + mi * 16;
                int n = n0 + c0 + (njj >> 2) * 32 + (njj & 3) * 8;
                const float* ac = acc[mi * 8 + njj];
                float b0v = bias[n], b1v = bias[n + 1];
                float2 v0 = make_float2(ac[0] + b0v, ac[1] + b1v);
                float2 v1 = make_float2(ac[2] + b0v, ac[3] + b1v);
                *(float2*)&Of[(size_t)m * HID + n]       = v0;
                *(float2*)&Of[(size_t)(m + 8) * HID + n] = v1;
            }
        return;
    }

    /* transposed fp16 write via fp16 stage [128][136] */
    __syncthreads();
    __half* hst = (__half*)smem;
#pragma unroll
    for (int mi = 0; mi < 2; mi++)
#pragma unroll
        for (int njj = 0; njj < 8; njj++) {
            int r  = wm * 32 + mi * 16 + (lane >> 2);
            int cn = wn * 64 + (njj >> 2) * 32 + (njj & 3) * 8 + (lane & 3) * 2;
            const float* ac = acc[mi * 8 + njj];
            *(half2*)&hst[r * 136 + cn]       = __floats2half2_rn(ac[0], ac[1]);
            *(half2*)&hst[(r + 8) * 136 + cn] = __floats2half2_rn(ac[2], ac[3]);
        }
    __syncthreads();

    int n  = tid & 127;
    int sh = tid >> 7;
    int ng = n0 + n;
    int h  = ng >> 6, d = ng & 63;
    int b  = m0 >> 9;
    int s  = (m0 & 511) + sh * 64;
    size_t R = ((size_t)b * HEADS + h) * DH + d;
    __half* dh = Oh + R * SEQ + s;
#pragma unroll
    for (int q = 0; q < 8; q++) {
        __align__(16) __half hv[8];
#pragma unroll
        for (int j = 0; j < 8; j++)
            hv[j] = hst[(sh * 64 + q * 8 + j) * 136 + n];
        *(uint4*)(dh + q * 8) = *(const uint4*)hv;
    }
}

/* ---------------------------- mix tensor GEMM ----------------------------- */
__global__ void __launch_bounds__(256, 2) gemm_mix_kernel(
    const __half* __restrict__ X, const __half* __restrict__ Mt,
    const float* __restrict__ bias, __half* __restrict__ Oh, int b_base)
{
    extern __shared__ __align__(16) char smem[];
    uint32_t sb = smem_u32(smem);
    int tid = threadIdx.x, lane = tid & 31, wid = tid >> 5;
    int wm = wid & 3, wn = wid >> 2;
    int t0 = blockIdx.x * 128;
    int h  = blockIdx.y;
    int b0 = b_base + blockIdx.z * 2;

    const __half* Mh = Mt + (size_t)h * SEQ * SEQ;

    float acc[16][4];
#pragma unroll
    for (int i = 0; i < 16; i++)
#pragma unroll
        for (int j = 0; j < 4; j++) acc[i][j] = 0.f;

    const int NK = SEQ / KT;   /* 16 */
    stage_load_mix(sb,          Mh, X, t0, h, b0, 0);  cp_commit();
    stage_load_mix(sb + STAGEB, Mh, X, t0, h, b0, KT); cp_commit();

    for (int i = 0; i < NK; i++) {
        if (i + 1 < NK) cp_wait1(); else cp_wait0();
        if ((i & 1) == 0) __syncthreads();
        uint32_t sbase = sb + (i & 3) * STAGEB;
        uint32_t af[8], bf[16];
        load_frags(sbase, 0, wm, wn, lane, af, bf);
        if (i + 2 < NK) {
            stage_load_mix(sb + ((i + 2) & 3) * STAGEB, Mh, X, t0, h, b0, (i + 2) * KT);
            cp_commit();
        }
        mma_frags(acc, af, bf);
        load_frags(sbase, 1, wm, wn, lane, af, bf);
        mma_frags(acc, af, bf);
    }

    /* direct reg -> global: bias + relu + cvt, half2 stores */
    const int r0 = wm * 32 + (lane >> 2);
    const int c0 = wn * 64 + (lane & 3) * 2;
#pragma unroll
    for (int mi = 0; mi < 2; mi++)
#pragma unroll
        for (int njj = 0; njj < 8; njj++) {
            int m = t0 + r0 + mi * 16;
            int n = c0 + (njj >> 2) * 32 + (njj & 3) * 8;   /* 0..127 */
            int bb = n >> 6, d = n & 63;
            int col = h * DH + d;
            const float* ac = acc[mi * 8 + njj];
            float b0v = bias[col], b1v = bias[col + 1];
            size_t rowg = (size_t)(b0 + bb) * SEQ + m;
            half2 v0 = __floats2half2_rn(fmaxf(ac[0] + b0v, 0.f), fmaxf(ac[1] + b1v, 0.f));
            half2 v1 = __floats2half2_rn(fmaxf(ac[2] + b0v, 0.f), fmaxf(ac[3] + b1v, 0.f));
            *(half2*)&Oh[rowg * HID + col]       = v0;
            *(half2*)&Oh[(rowg + 8) * HID + col] = v1;
        }
}

/* --------------------------- conversion kernels --------------------------- */
__global__ void __launch_bounds__(256) cvt_hi_kernel(
    const float* __restrict__ s, __half* __restrict__ dh, int n4)
{
    for (int i = blockIdx.x * 256 + threadIdx.x; i < n4; i += gridDim.x * 256) {
        float4 v = ((const float4*)s)[i];
        __align__(8) __half o[4];
        o[0] = __float2half_rn(v.x); o[1] = __float2half_rn(v.y);
        o[2] = __float2half_rn(v.z); o[3] = __float2half_rn(v.w);
        ((uint2*)dh)[i] = *(const uint2*)o;
    }
}

/* Mt[l,h,t,s] = M[l,h,s,t]; 64s x 32t tiles (128B store rows), z-batch 4. */
__global__ void __launch_bounds__(256) transpose_cvt_kernel(
    const float* __restrict__ M, __half* __restrict__ th)
{
    __shared__ float tile[64][33];
    int s0 = blockIdx.x * 64, t0 = blockIdx.y * 32;
    int tx = threadIdx.x & 31, ty = threadIdx.x >> 5;
    int wt = threadIdx.x >> 3;          /* t index 0..31 */
    int sq = (threadIdx.x & 7) * 8;     /* s octet base  */
#pragma unroll 1
    for (int zz = 0; zz < 4; zz++) {
        int z = blockIdx.z * 4 + zz;
        const float* src = M + (size_t)z * SEQ * SEQ;
        size_t ob = (size_t)z * SEQ * SEQ;
#pragma unroll
        for (int i = ty; i < 64; i += 8)
            tile[i][tx] = src[(size_t)(s0 + i) * SEQ + t0 + tx];
        __syncthreads();
        __align__(16) __half o[8];
#pragma unroll
        for (int j = 0; j < 8; j++)
            o[j] = __float2half_rn(tile[sq + j][wt]);
        *(uint4*)&th[ob + (size_t)(t0 + wt) * SEQ + s0 + sq] = *(const uint4*)o;
        __syncthreads();
    }
}

__global__ void __launch_bounds__(256) embed_ln_kernel(
    const int* __restrict__ x,
    const float* __restrict__ we, const float* __restrict__ pe,
    const float* __restrict__ te,
    const float* __restrict__ g, const float* __restrict__ beta,
    __half* __restrict__ oh)
{
    int row = blockIdx.x;
    int s   = row & (SEQ - 1);
    int tok = x[row];
    const float* w = we + (size_t)tok * HID;
    const float* p = pe + (size_t)s * HID;

    float v[3];
    float sum = 0.f;
#pragma unroll
    for (int i = 0; i < 3; i++) {
        int c = threadIdx.x + i * 256;
        v[i] = w[c] + p[c] + te[c];
        sum += v[i];
    }

    __shared__ float red[8];
    __shared__ float s_mu, s_rs;
#pragma unroll
    for (int o = 16; o > 0; o >>= 1) sum += __shfl_down_sync(0xffffffffu, sum, o);
    if ((threadIdx.x & 31) == 0) red[threadIdx.x >> 5] = sum;
    __syncthreads();
    if (threadIdx.x == 0) {
        float t = 0.f;
#pragma unroll
        for (int i = 0; i < 8; i++) t += red[i];
        s_mu = t * (1.f / HID);
    }
    __syncthreads();
    float mu = s_mu;

    float sq = 0.f;
#pragma unroll
    for (int i = 0; i < 3; i++) { float d = v[i] - mu; sq += d * d; }
#pragma unroll
    for (int o = 16; o > 0; o >>= 1) sq += __shfl_down_sync(0xffffffffu, sq, o);
    if ((threadIdx.x & 31) == 0) red[threadIdx.x >> 5] = sq;
    __syncthreads();
    if (threadIdx.x == 0) {
        float t = 0.f;
#pragma unroll
        for (int i = 0; i < 8; i++) t += red[i];
        s_rs = rsqrtf(t * (1.f / HID) + LN_EPS);
    }
    __syncthreads();
    float rs = s_rs;

#pragma unroll
    for (int i = 0; i < 3; i++) {
        int c = threadIdx.x + i * 256;
        float val = (v[i] - mu) * rs * g[c] + beta[c];
        oh[(size_t)row * HID + c] = __float2half_rn(val);
    }
}

/* --------------------------------- launch --------------------------------- */
extern "C" void kernel_launch(void* const* d_in, const int* in_sizes, int n_in,
                              void* d_out, int out_size)
{
    const int*   x   = (const int*)d_in[0];
    const float* we  = (const float*)d_in[1];
    const float* pe  = (const float*)d_in[2];
    const float* te  = (const float*)d_in[3];
    const float* lng = (const float*)d_in[4];
    const float* lnb = (const float*)d_in[5];
    const float* W   = (const float*)d_in[6];
    const float* bi  = (const float*)d_in[7];
    const float* Mm  = (const float*)d_in[8];
    const float* lw  = (const float*)d_in[9];
    const float* lb  = (const float*)d_in[10];
    float* out = (float*)d_out;

    __half *hA, *Xt, *Wh, *Mt;
    cudaGetSymbolAddress((void**)&hA, g_hA);
    cudaGetSymbolAddress((void**)&Xt, g_Xt);
    cudaGetSymbolAddress((void**)&Wh, g_W);
    cudaGetSymbolAddress((void**)&Mt, g_Mt);

    cudaFuncSetAttribute(gemm_dense_kernel<false>,
                         cudaFuncAttributeMaxDynamicSharedMemorySize, SMEM_DYN);
    cudaFuncSetAttribute(gemm_dense_kernel<true>,
                         cudaFuncAttributeMaxDynamicSharedMemorySize, SMEM_DYN);
    cudaFuncSetAttribute(gemm_mix_kernel,
                         cudaFuncAttributeMaxDynamicSharedMemorySize, SMEM_DYN);

    /* forked prologue: W0 | bulk W | Mt-transpose | embed run concurrently */
    cudaEventRecord(g_fork.fork, 0);

    cudaStreamWaitEvent(g_fork.p[0], g_fork.fork, 0);
    cvt_hi_kernel<<<64, 256, 0, g_fork.p[0]>>>(W, Wh, HID * HID / 4);  /* layer 0 */
    cudaEventRecord(g_fork.w0, g_fork.p[0]);
    cvt_hi_kernel<<<1024, 256, 0, g_fork.p[0]>>>(
        W + (size_t)HID * HID, Wh + (size_t)HID * HID,
        (LAYERS - 1) * HID * HID / 4);
    cvt_hi_kernel<<<144, 256, 0, g_fork.p[0]>>>(
        lw, Wh + (size_t)LAYERS * HID * HID, HID * HID / 4);
    cudaEventRecord(g_fork.pro0, g_fork.p[0]);

    cudaStreamWaitEvent(g_fork.p[1], g_fork.fork, 0);
    {
        dim3 tb(256), tg(SEQ / 64, SEQ / 32, LAYERS * HEADS / 4);
        transpose_cvt_kernel<<<tg, tb, 0, g_fork.p[1]>>>(Mm, Mt);
    }
    cudaEventRecord(g_fork.pro1, g_fork.p[1]);

    embed_ln_kernel<<<ROWS, 256>>>(x, we, pe, te, lng, lnb, hA);
    cudaEventRecord(g_fork.emb, 0);

    /* fork: NGRP independent batch-group chains */
    dim3 gd(HID / 128, ROWS / 128 / NGRP);         /* (6, 16)    */
    dim3 gm(SEQ / 128, HEADS, BATCH / 2 / NGRP);   /* (4, 12, 2) */

    for (int g = 0; g < NGRP; g++) {
        cudaStream_t st = g_fork.s[g];
        int m_base = g * (ROWS / NGRP);
        int b_base = g * GBATCH;

        cudaStreamWaitEvent(st, g_fork.emb, 0);
        cudaStreamWaitEvent(st, g_fork.w0, 0);
        gemm_dense_kernel<false><<<gd, 256, SMEM_DYN, st>>>(
            hA, Wh, nullptr, Xt, nullptr, m_base);

        cudaStreamWaitEvent(st, g_fork.pro1, 0);
        gemm_mix_kernel<<<gm, 256, SMEM_DYN, st>>>(
            Xt, Mt, bi, hA, b_base);

        cudaStreamWaitEvent(st, g_fork.pro0, 0);
        for (int l = 1; l < LAYERS; l++) {
            gemm_dense_kernel<false><<<gd, 256, SMEM_DYN, st>>>(
                hA, Wh + (size_t)l * HID * HID, nullptr, Xt, nullptr, m_base);
            gemm_mix_kernel<<<gm, 256, SMEM_DYN, st>>>(
                Xt, Mt + (size_t)l * HEADS * SEQ * SEQ,
                bi + (size_t)l * HID, hA, b_base);
        }
        gemm_dense_kernel<true><<<gd, 256, SMEM_DYN, st>>>(
            hA, Wh + (size_t)LAYERS * HID * HID, lb, nullptr, out, m_base);
        cudaEventRecord(g_fork.join[g], st);
    }
    /* join back onto the capture stream */
    for (int g = 0; g < NGRP; g++)
        cudaStreamWaitEvent(0, g_fork.join[g], 0);
}

// round 17
// speedup vs baseline: 1.0293x; 1.0293x over previous
#include <cuda_runtime.h>
#include <cuda_fp16.h>
#include <stdint.h>

#define SEQ    512
#define HID    768
#define HEADS  12
#define DH     64
#define LAYERS 12
#define BATCH  32
#define ROWS   (BATCH * SEQ)   /* 16384 */
#define LN_EPS 1e-12f

#define KT   32                 /* fp16 k per stage            */
#define RSE  40                 /* A smem row stride, elements */
#define RSB  80                 /* A smem row stride, bytes    */
#define BUFB (128 * RSB)        /* A buffer: 10240 B           */
#define BROW 272                /* mix B row stride, bytes (136 elems) */
#define STAGEB (2 * BUFB)       /* 20480 B (covers dense A+B; mix A+B=18944) */
#define NSTAGE 4
#define OFF_A 0
#define OFF_B BUFB
#define SMEM_DYN (NSTAGE * STAGEB)   /* 81920 B */

#define NGRP 8                  /* batch groups (parallel graph branches) */
#define GBATCH (BATCH / NGRP)   /* 4 batches per group */

/* ------------------------- device scratch (static) ------------------------ */
__device__ __half g_hA[(size_t)ROWS * HID];
__device__ __half g_hB[(size_t)ROWS * HID];   /* dense output, row-major */
__device__ __half g_W[(size_t)(LAYERS + 1) * HID * HID];
__device__ __half g_Mt[(size_t)LAYERS * HEADS * SEQ * SEQ];

/* ---------------- streams/events (created at static init) ----------------- */
struct GraphForkRes {
    cudaStream_t s[NGRP];
    cudaStream_t p[2];
    cudaEvent_t  fork;
    cudaEvent_t  w0;      /* layer-0 W converted      */
    cudaEvent_t  pro0;    /* all W converted          */
    cudaEvent_t  pro1;    /* Mt transposed            */
    cudaEvent_t  join[NGRP];
    GraphForkRes() {
        for (int i = 0; i < NGRP; i++)
            cudaStreamCreateWithFlags(&s[i], cudaStreamNonBlocking);
        for (int i = 0; i < 2; i++)
            cudaStreamCreateWithFlags(&p[i], cudaStreamNonBlocking);
        cudaEventCreateWithFlags(&fork, cudaEventDisableTiming);
        cudaEventCreateWithFlags(&w0, cudaEventDisableTiming);
        cudaEventCreateWithFlags(&pro0, cudaEventDisableTiming);
        cudaEventCreateWithFlags(&pro1, cudaEventDisableTiming);
        for (int i = 0; i < NGRP; i++)
            cudaEventCreateWithFlags(&join[i], cudaEventDisableTiming);
    }
};
static GraphForkRes g_fork;

/* ------------------------------ PTX helpers ------------------------------ */
__device__ __forceinline__ uint32_t smem_u32(const void* p) {
    uint32_t a;
    asm("{ .reg .u64 t; cvta.to.shared.u64 t, %1; cvt.u32.u64 %0, t; }"
        : "=r"(a) : "l"(p));
    return a;
}
__device__ __forceinline__ void cpa16(uint32_t dst, const void* src) {
    asm volatile("cp.async.cg.shared.global [%0], [%1], 16;"
                 :: "r"(dst), "l"(src) : "memory");
}
__device__ __forceinline__ void cp_commit() {
    asm volatile("cp.async.commit_group;" ::: "memory");
}
__device__ __forceinline__ void cp_wait1() {
    asm volatile("cp.async.wait_group 1;" ::: "memory");
}
__device__ __forceinline__ void cp_wait0() {
    asm volatile("cp.async.wait_group 0;" ::: "memory");
}
__device__ __forceinline__ void ldm_x4(uint32_t* r, uint32_t addr) {
    asm volatile("ldmatrix.sync.aligned.m8n8.x4.shared.b16 {%0,%1,%2,%3}, [%4];"
                 : "=r"(r[0]), "=r"(r[1]), "=r"(r[2]), "=r"(r[3]) : "r"(addr));
}
__device__ __forceinline__ void ldm_x4t(uint32_t* r, uint32_t addr) {
    asm volatile("ldmatrix.sync.aligned.m8n8.x4.trans.shared.b16 {%0,%1,%2,%3}, [%4];"
                 : "=r"(r[0]), "=r"(r[1]), "=r"(r[2]), "=r"(r[3]) : "r"(addr));
}
__device__ __forceinline__ void mma16816(float* c, const uint32_t* a, const uint32_t* b) {
    asm volatile(
        "mma.sync.aligned.m16n8k16.row.col.f32.f16.f16.f32 "
        "{%0,%1,%2,%3},{%4,%5,%6,%7},{%8,%9},{%0,%1,%2,%3};"
        : "+f"(c[0]), "+f"(c[1]), "+f"(c[2]), "+f"(c[3])
        : "r"(a[0]), "r"(a[1]), "r"(a[2]), "r"(a[3]), "r"(b[0]), "r"(b[1]));
}

/* ------------------------------ stage loaders ----------------------------- */
__device__ __forceinline__ void stage_load_dense(
    uint32_t sm, const __half* A, const __half* W, int m0, int n0, int k0)
{
    int tid = threadIdx.x;
#pragma unroll
    for (int i = 0; i < 4; i++) {
        const int buf = i >> 1;
        int rem = tid + (i & 1) * 256;
        int row = rem >> 2;
        int c   = rem & 3;
        const __half* src = buf
            ? W + (size_t)(n0 + row) * HID + k0 + c * 8
            : A + (size_t)(m0 + row) * HID + k0 + c * 8;
        cpa16(sm + buf * BUFB + row * RSB + c * 16, src);
    }
}
/* Mix: A = Mt tile [t=128][k=32]; B = X tile [k=32][n=128] (d-contiguous rows) */
__device__ __forceinline__ void stage_load_mix(
    uint32_t sm, const __half* M, const __half* X,
    int t0, int h, int b0, int s0)
{
    int tid = threadIdx.x;
#pragma unroll
    for (int i = 0; i < 4; i++) {
        if (i < 2) {   /* A: 512 chunks */
            int id = tid + i * 256;
            int row = id >> 2, c = id & 3;
            cpa16(sm + row * RSB + c * 16,
                  M + (size_t)(t0 + row) * SEQ + s0 + c * 8);
        } else {       /* B: 512 chunks: (bb, s, c) */
            int id = tid + (i - 2) * 256;
            int bb = id >> 8, rem = id & 255;
            int s = rem >> 3, c = rem & 7;
            cpa16(sm + OFF_B + s * BROW + bb * 128 + c * 16,
                  X + ((size_t)(b0 + bb) * SEQ + s0 + s) * HID + h * DH + c * 8);
        }
    }
}

/* ------------------------------- MMA core -------------------------------- */
/* 8 warps, each 32m x 64n; acc[16][4]. */
__device__ __forceinline__ void load_frags_a(
    uint32_t sbase, int ks, int wm, int lane, uint32_t* af)
{
    const int ar = lane & 15;
    const int ac = (lane >> 4) * 8;
#pragma unroll
    for (int mi = 0; mi < 2; mi++) {
        uint32_t off = ((wm * 32 + mi * 16 + ar) * RSE + ks * 16 + ac) * 2;
        ldm_x4(af + 4 * mi, sbase + OFF_A + off);
    }
}
/* dense B: W rows [n][k], non-trans */
__device__ __forceinline__ void load_frags_b_dense(
    uint32_t sbase, int ks, int wn, int lane, uint32_t* bf)
{
    const int br = ((lane >> 4) << 3) + (lane & 7);
    const int bc = ((lane >> 3) & 1) * 8;
#pragma unroll
    for (int nh = 0; nh < 2; nh++)
#pragma unroll
        for (int g = 0; g < 2; g++) {
            uint32_t off = ((wn * 64 + nh * 32 + g * 16 + br) * RSE + ks * 16 + bc) * 2;
            ldm_x4(bf + nh * 8 + 4 * g, sbase + OFF_B + off);
        }
}
/* mix B: X tile [k][n], ldmatrix.trans; q-th x4 covers n16 at wn*64+q*16 */
__device__ __forceinline__ void load_frags_b_mix(
    uint32_t sbase, int ks, int wn, int lane, uint32_t* bf)
{
    const int row = ks * 16 + (lane & 15);
    const int colb = (lane >> 4) * 8;
#pragma unroll
    for (int q = 0; q < 4; q++) {
        uint32_t off = OFF_B + (uint32_t)row * BROW + (wn * 64 + q * 16 + colb) * 2;
        ldm_x4t(bf + 4 * q, sbase + off);
    }
}
__device__ __forceinline__ void mma_frags(
    float (*acc)[4], const uint32_t* af, const uint32_t* bf)
{
#pragma unroll
    for (int nh = 0; nh < 2; nh++)
#pragma unroll
        for (int mi = 0; mi < 2; mi++)
#pragma unroll
            for (int nj = 0; nj < 4; nj++)
                mma16816(acc[mi * 8 + nh * 4 + nj], af + 4 * mi, bf + nh * 8 + 2 * nj);
}

/* --------------------------- dense tensor GEMM ---------------------------- */
template <bool FINAL>
__global__ void __launch_bounds__(256, 2) gemm_dense_kernel(
    const __half* __restrict__ A, const __half* __restrict__ W,
    const float* __restrict__ bias,
    __half* __restrict__ Oh, float* __restrict__ Of, int m_base)
{
    extern __shared__ __align__(16) char smem[];
    uint32_t sb = smem_u32(smem);
    int tid = threadIdx.x, lane = tid & 31, wid = tid >> 5;
    int wm = wid & 3, wn = wid >> 2;
    int n0 = blockIdx.x * 128, m0 = m_base + blockIdx.y * 128;

    float acc[16][4];
#pragma unroll
    for (int i = 0; i < 16; i++)
#pragma unroll
        for (int j = 0; j < 4; j++) acc[i][j] = 0.f;

    const int NK = HID / KT;   /* 24 */
    stage_load_dense(sb,          A, W, m0, n0, 0);  cp_commit();
    stage_load_dense(sb + STAGEB, A, W, m0, n0, KT); cp_commit();

    for (int i = 0; i < NK; i++) {
        if (i + 1 < NK) cp_wait1(); else cp_wait0();
        if ((i & 1) == 0) __syncthreads();
        uint32_t sbase = sb + (i & 3) * STAGEB;
        uint32_t af[8], bf[16];
        load_frags_a(sbase, 0, wm, lane, af);
        load_frags_b_dense(sbase, 0, wn, lane, bf);
        if (i + 2 < NK) {
            stage_load_dense(sb + ((i + 2) & 3) * STAGEB, A, W, m0, n0, (i + 2) * KT);
            cp_commit();
        }
        mma_frags(acc, af, bf);
        load_frags_a(sbase, 1, wm, lane, af);
        load_frags_b_dense(sbase, 1, wn, lane, bf);
        mma_frags(acc, af, bf);
    }

    const int r0 = wm * 32 + (lane >> 2);
    const int c0 = wn * 64 + (lane & 3) * 2;
    if (FINAL) {
#pragma unroll
        for (int mi = 0; mi < 2; mi++)
#pragma unroll
            for (int njj = 0; njj < 8; njj++) {
                int m = m0 + r0 + mi * 16;
                int n = n0 + c0 + (njj >> 2) * 32 + (njj & 3) * 8;
                const float* ac = acc[mi * 8 + njj];
                float b0v = bias[n], b1v = bias[n + 1];
                float2 v0 = make_float2(ac[0] + b0v, ac[1] + b1v);
                float2 v1 = make_float2(ac[2] + b0v, ac[3] + b1v);
                *(float2*)&Of[(size_t)m * HID + n]       = v0;
                *(float2*)&Of[(size_t)(m + 8) * HID + n] = v1;
            }
    } else {
        /* direct row-major fp16 write (no staging) */
#pragma unroll
        for (int mi = 0; mi < 2; mi++)
#pragma unroll
            for (int njj = 0; njj < 8; njj++) {
                int m = m0 + r0 + mi * 16;
                int n = n0 + c0 + (njj >> 2) * 32 + (njj & 3) * 8;
                const float* ac = acc[mi * 8 + njj];
                *(half2*)&Oh[(size_t)m * HID + n]       = __floats2half2_rn(ac[0], ac[1]);
                *(half2*)&Oh[(size_t)(m + 8) * HID + n] = __floats2half2_rn(ac[2], ac[3]);
            }
    }
}

/* ---------------------------- mix tensor GEMM ----------------------------- */
/* Out[b0+bb, t0+t, h*64+d] = relu( sum_s Mt[h,t,s] * X[b,s,h*64+d] + bias ),
   A = Mt (row-major t x s), B = X tile [s][d] via ldmatrix.trans. */
__global__ void __launch_bounds__(256, 2) gemm_mix_kernel(
    const __half* __restrict__ X, const __half* __restrict__ Mt,
    const float* __restrict__ bias, __half* __restrict__ Oh, int b_base)
{
    extern __shared__ __align__(16) char smem[];
    uint32_t sb = smem_u32(smem);
    int tid = threadIdx.x, lane = tid & 31, wid = tid >> 5;
    int wm = wid & 3, wn = wid >> 2;
    int t0 = blockIdx.x * 128;
    int h  = blockIdx.y;
    int b0 = b_base + blockIdx.z * 2;

    const __half* Mh = Mt + (size_t)h * SEQ * SEQ;

    float acc[16][4];
#pragma unroll
    for (int i = 0; i < 16; i++)
#pragma unroll
        for (int j = 0; j < 4; j++) acc[i][j] = 0.f;

    const int NK = SEQ / KT;   /* 16 */
    stage_load_mix(sb,          Mh, X, t0, h, b0, 0);  cp_commit();
    stage_load_mix(sb + STAGEB, Mh, X, t0, h, b0, KT); cp_commit();

    for (int i = 0; i < NK; i++) {
        if (i + 1 < NK) cp_wait1(); else cp_wait0();
        if ((i & 1) == 0) __syncthreads();
        uint32_t sbase = sb + (i & 3) * STAGEB;
        uint32_t af[8], bf[16];
        load_frags_a(sbase, 0, wm, lane, af);
        load_frags_b_mix(sbase, 0, wn, lane, bf);
        if (i + 2 < NK) {
            stage_load_mix(sb + ((i + 2) & 3) * STAGEB, Mh, X, t0, h, b0, (i + 2) * KT);
            cp_commit();
        }
        mma_frags(acc, af, bf);
        load_frags_a(sbase, 1, wm, lane, af);
        load_frags_b_mix(sbase, 1, wn, lane, bf);
        mma_frags(acc, af, bf);
    }

    /* direct reg -> global: bias + relu + cvt, half2 stores */
    const int r0 = wm * 32 + (lane >> 2);
    const int c0 = wn * 64 + (lane & 3) * 2;
#pragma unroll
    for (int mi = 0; mi < 2; mi++)
#pragma unroll
        for (int njj = 0; njj < 8; njj++) {
            int m = t0 + r0 + mi * 16;
            int n = c0 + (njj >> 2) * 32 + (njj & 3) * 8;   /* 0..127 */
            int bb = n >> 6, d = n & 63;
            int col = h * DH + d;
            const float* ac = acc[mi * 8 + njj];
            float b0v = bias[col], b1v = bias[col + 1];
            size_t rowg = (size_t)(b0 + bb) * SEQ + m;
            half2 v0 = __floats2half2_rn(fmaxf(ac[0] + b0v, 0.f), fmaxf(ac[1] + b1v, 0.f));
            half2 v1 = __floats2half2_rn(fmaxf(ac[2] + b0v, 0.f), fmaxf(ac[3] + b1v, 0.f));
            *(half2*)&Oh[rowg * HID + col]       = v0;
            *(half2*)&Oh[(rowg + 8) * HID + col] = v1;
        }
}

/* --------------------------- conversion kernels --------------------------- */
__global__ void __launch_bounds__(256) cvt_hi_kernel(
    const float* __restrict__ s, __half* __restrict__ dh, int n4)
{
    for (int i = blockIdx.x * 256 + threadIdx.x; i < n4; i += gridDim.x * 256) {
        float4 v = ((const float4*)s)[i];
        __align__(8) __half o[4];
        o[0] = __float2half_rn(v.x); o[1] = __float2half_rn(v.y);
        o[2] = __float2half_rn(v.z); o[3] = __float2half_rn(v.w);
        ((uint2*)dh)[i] = *(const uint2*)o;
    }
}

/* Mt[l,h,t,s] = M[l,h,s,t]; 64s x 32t tiles (128B store rows), z-batch 4. */
__global__ void __launch_bounds__(256) transpose_cvt_kernel(
    const float* __restrict__ M, __half* __restrict__ th)
{
    __shared__ float tile[64][33];
    int s0 = blockIdx.x * 64, t0 = blockIdx.y * 32;
    int tx = threadIdx.x & 31, ty = threadIdx.x >> 5;
    int wt = threadIdx.x >> 3;
    int sq = (threadIdx.x & 7) * 8;
#pragma unroll 1
    for (int zz = 0; zz < 4; zz++) {
        int z = blockIdx.z * 4 + zz;
        const float* src = M + (size_t)z * SEQ * SEQ;
        size_t ob = (size_t)z * SEQ * SEQ;
#pragma unroll
        for (int i = ty; i < 64; i += 8)
            tile[i][tx] = src[(size_t)(s0 + i) * SEQ + t0 + tx];
        __syncthreads();
        __align__(16) __half o[8];
#pragma unroll
        for (int j = 0; j < 8; j++)
            o[j] = __float2half_rn(tile[sq + j][wt]);
        *(uint4*)&th[ob + (size_t)(t0 + wt) * SEQ + s0 + sq] = *(const uint4*)o;
        __syncthreads();
    }
}

__global__ void __launch_bounds__(256) embed_ln_kernel(
    const int* __restrict__ x,
    const float* __restrict__ we, const float* __restrict__ pe,
    const float* __restrict__ te,
    const float* __restrict__ g, const float* __restrict__ beta,
    __half* __restrict__ oh, int row_base)
{
    int row = row_base + blockIdx.x;
    int s   = row & (SEQ - 1);
    int tok = x[row];
    const float* w = we + (size_t)tok * HID;
    const float* p = pe + (size_t)s * HID;

    float v[3];
    float sum = 0.f;
#pragma unroll
    for (int i = 0; i < 3; i++) {
        int c = threadIdx.x + i * 256;
        v[i] = w[c] + p[c] + te[c];
        sum += v[i];
    }

    __shared__ float red[8];
    __shared__ float s_mu, s_rs;
#pragma unroll
    for (int o = 16; o > 0; o >>= 1) sum += __shfl_down_sync(0xffffffffu, sum, o);
    if ((threadIdx.x & 31) == 0) red[threadIdx.x >> 5] = sum;
    __syncthreads();
    if (threadIdx.x == 0) {
        float t = 0.f;
#pragma unroll
        for (int i = 0; i < 8; i++) t += red[i];
        s_mu = t * (1.f / HID);
    }
    __syncthreads();
    float mu = s_mu;

    float sq = 0.f;
#pragma unroll
    for (int i = 0; i < 3; i++) { float d = v[i] - mu; sq += d * d; }
#pragma unroll
    for (int o = 16; o > 0; o >>= 1) sq += __shfl_down_sync(0xffffffffu, sq, o);
    if ((threadIdx.x & 31) == 0) red[threadIdx.x >> 5] = sq;
    __syncthreads();
    if (threadIdx.x == 0) {
        float t = 0.f;
#pragma unroll
        for (int i = 0; i < 8; i++) t += red[i];
        s_rs = rsqrtf(t * (1.f / HID) + LN_EPS);
    }
    __syncthreads();
    float rs = s_rs;

#pragma unroll
    for (int i = 0; i < 3; i++) {
        int c = threadIdx.x + i * 256;
        float val = (v[i] - mu) * rs * g[c] + beta[c];
        oh[(size_t)row * HID + c] = __float2half_rn(val);
    }
}

/* --------------------------------- launch --------------------------------- */
extern "C" void kernel_launch(void* const* d_in, const int* in_sizes, int n_in,
                              void* d_out, int out_size)
{
    const int*   x   = (const int*)d_in[0];
    const float* we  = (const float*)d_in[1];
    const float* pe  = (const float*)d_in[2];
    const float* te  = (const float*)d_in[3];
    const float* lng = (const float*)d_in[4];
    const float* lnb = (const float*)d_in[5];
    const float* W   = (const float*)d_in[6];
    const float* bi  = (const float*)d_in[7];
    const float* Mm  = (const float*)d_in[8];
    const float* lw  = (const float*)d_in[9];
    const float* lb  = (const float*)d_in[10];
    float* out = (float*)d_out;

    __half *hA, *hB, *Wh, *Mt;
    cudaGetSymbolAddress((void**)&hA, g_hA);
    cudaGetSymbolAddress((void**)&hB, g_hB);
    cudaGetSymbolAddress((void**)&Wh, g_W);
    cudaGetSymbolAddress((void**)&Mt, g_Mt);

    cudaFuncSetAttribute(gemm_dense_kernel<false>,
                         cudaFuncAttributeMaxDynamicSharedMemorySize, SMEM_DYN);
    cudaFuncSetAttribute(gemm_dense_kernel<true>,
                         cudaFuncAttributeMaxDynamicSharedMemorySize, SMEM_DYN);
    cudaFuncSetAttribute(gemm_mix_kernel,
                         cudaFuncAttributeMaxDynamicSharedMemorySize, SMEM_DYN);

    /* forked prologue: W0 | bulk W | Mt-transpose run concurrently */
    cudaEventRecord(g_fork.fork, 0);

    cudaStreamWaitEvent(g_fork.p[0], g_fork.fork, 0);
    cvt_hi_kernel<<<64, 256, 0, g_fork.p[0]>>>(W, Wh, HID * HID / 4);  /* layer 0 */
    cudaEventRecord(g_fork.w0, g_fork.p[0]);
    cvt_hi_kernel<<<1024, 256, 0, g_fork.p[0]>>>(
        W + (size_t)HID * HID, Wh + (size_t)HID * HID,
        (LAYERS - 1) * HID * HID / 4);
    cvt_hi_kernel<<<144, 256, 0, g_fork.p[0]>>>(
        lw, Wh + (size_t)LAYERS * HID * HID, HID * HID / 4);
    cudaEventRecord(g_fork.pro0, g_fork.p[0]);

    cudaStreamWaitEvent(g_fork.p[1], g_fork.fork, 0);
    {
        dim3 tb(256), tg(SEQ / 64, SEQ / 32, LAYERS * HEADS / 4);
        transpose_cvt_kernel<<<tg, tb, 0, g_fork.p[1]>>>(Mm, Mt);
    }
    cudaEventRecord(g_fork.pro1, g_fork.p[1]);

    /* fork: NGRP independent batch-group chains (each embeds its own rows) */
    dim3 gd(HID / 128, ROWS / 128 / NGRP);         /* (6, 16)    */
    dim3 gm(SEQ / 128, HEADS, BATCH / 2 / NGRP);   /* (4, 12, 2) */

    for (int g = 0; g < NGRP; g++) {
        cudaStream_t st = g_fork.s[g];
        int m_base = g * (ROWS / NGRP);
        int b_base = g * GBATCH;

        cudaStreamWaitEvent(st, g_fork.fork, 0);
        embed_ln_kernel<<<ROWS / NGRP, 256, 0, st>>>(
            x, we, pe, te, lng, lnb, hA, m_base);

        cudaStreamWaitEvent(st, g_fork.w0, 0);
        gemm_dense_kernel<false><<<gd, 256, SMEM_DYN, st>>>(
            hA, Wh, nullptr, hB, nullptr, m_base);

        cudaStreamWaitEvent(st, g_fork.pro1, 0);
        gemm_mix_kernel<<<gm, 256, SMEM_DYN, st>>>(
            hB, Mt, bi, hA, b_base);

        cudaStreamWaitEvent(st, g_fork.pro0, 0);
        for (int l = 1; l < LAYERS; l++) {
            gemm_dense_kernel<false><<<gd, 256, SMEM_DYN, st>>>(
                hA, Wh + (size_t)l * HID * HID, nullptr, hB, nullptr, m_base);
            gemm_mix_kernel<<<gm, 256, SMEM_DYN, st>>>(
                hB, Mt + (size_t)l * HEADS * SEQ * SEQ,
                bi + (size_t)l * HID, hA, b_base);
        }
        gemm_dense_kernel<true><<<gd, 256, SMEM_DYN, st>>>(
            hA, Wh + (size_t)LAYERS * HID * HID, lb, nullptr, out, m_base);
        cudaEventRecord(g_fork.join[g], st);
    }
    /* join back onto the capture stream */
    for (int g = 0; g < NGRP; g++)
        cudaStreamWaitEvent(0, g_fork.join[g], 0);
}